// round 1
// baseline (speedup 1.0000x reference)
#include <cuda_runtime.h>

#define D 128
#define NA 100000
#define NB 150000
#define NG 2000
#define NTOT (NA + NB + NG)      // 252000
#define MAXN NB                  // largest n_dst
#define DEG_TOT 756000           // sum of n_src (= sum of n_dst) over all 9 relations
#define BN_EPS 1e-5f

// ---------------- device scratch (allocation-free contract) ----------------
__device__ float g_ns[DEG_TOT];                 // per-(rel,src-node) out-degree norm
__device__ float g_nd[DEG_TOT];                 // per-(rel,dst-node) in-degree norm
__device__ float g_m[(size_t)MAXN * D];         // aggregated messages
__device__ float g_gout[(size_t)MAXN * D];      // gemm output pre-BN
__device__ float g_feat[(size_t)NTOT * D];      // layer-0 accumulator -> layer-1 input
__device__ float g_acc[(size_t)NTOT * D];       // layer-1 accumulator
__device__ float g_stats[2 * D];                // col sum / sumsq
__device__ float g_scale[D];
__device__ float g_shift[D];

// ---------------- kernels ----------------
__global__ void k_zero4(float4* p, int n4) {
    int i = blockIdx.x * blockDim.x + threadIdx.x;
    if (i < n4) p[i] = make_float4(0.f, 0.f, 0.f, 0.f);
}

__global__ void k_count(const int* __restrict__ src, const int* __restrict__ dst,
                        int ne, float* __restrict__ cs, float* __restrict__ cd) {
    int e = blockIdx.x * blockDim.x + threadIdx.x;
    if (e < ne) {
        atomicAdd(&cs[src[e]], 1.f);
        atomicAdd(&cd[dst[e]], 1.f);
    }
}

__global__ void k_rsqrt(float* p, int n) {
    int i = blockIdx.x * blockDim.x + threadIdx.x;
    if (i < n) {
        float c = p[i];
        p[i] = (c > 0.f) ? rsqrtf(c) : 0.f;
    }
}

// one warp per edge: gather src row (scaled by ns), atomic-scatter into m[dst]
__global__ void k_scatter(const float* __restrict__ feat,
                          const int* __restrict__ src, const int* __restrict__ dst,
                          const float* __restrict__ ns, float* __restrict__ m, int ne) {
    int e = blockIdx.x * (blockDim.x >> 5) + (threadIdx.x >> 5);
    int lane = threadIdx.x & 31;
    if (e >= ne) return;
    int s = src[e];
    int d = dst[e];
    float w = ns[s];
    float4 v = *(const float4*)(feat + (size_t)s * D + lane * 4);
    float* md = m + (size_t)d * D + lane * 4;
    atomicAdd(md + 0, v.x * w);
    atomicAdd(md + 1, v.y * w);
    atomicAdd(md + 2, v.z * w);
    atomicAdd(md + 3, v.w * w);
}

// out = (A @ W) * nd[:,None] + bias; also accumulate column sum/sumsq for BN.
// BM=128, BN=128, BK=16, 256 threads, 8x8 per thread.
__global__ __launch_bounds__(256)
void k_gemm_bn(const float* __restrict__ A, const float* __restrict__ Wr,
               const float* __restrict__ nd, const float* __restrict__ bias,
               float* __restrict__ out, float* __restrict__ stats, int m) {
    __shared__ float As[16][128];   // [k][row]
    __shared__ float Bs[16][128];   // [k][col]
    __shared__ float s_sum[128];
    __shared__ float s_sq[128];

    int tid = threadIdx.x;
    int rowBase = blockIdx.x * 128;
    if (tid < 128) { s_sum[tid] = 0.f; s_sq[tid] = 0.f; }

    float acc[8][8];
#pragma unroll
    for (int i = 0; i < 8; i++)
#pragma unroll
        for (int j = 0; j < 8; j++) acc[i][j] = 0.f;

    int tRow = tid >> 4;   // 0..15
    int tCol = tid & 15;   // 0..15

    for (int k0 = 0; k0 < 128; k0 += 16) {
#pragma unroll
        for (int t = 0; t < 2; t++) {
            int idx = tid + t * 256;         // 0..511
            int r = idx >> 2;                // 0..127
            int k4 = (idx & 3) * 4;          // 0,4,8,12
            float4 v = make_float4(0.f, 0.f, 0.f, 0.f);
            int gr = rowBase + r;
            if (gr < m) v = *(const float4*)(A + (size_t)gr * 128 + k0 + k4);
            As[k4 + 0][r] = v.x;
            As[k4 + 1][r] = v.y;
            As[k4 + 2][r] = v.z;
            As[k4 + 3][r] = v.w;
        }
#pragma unroll
        for (int t = 0; t < 2; t++) {
            int idx = tid + t * 256;
            int kr = idx >> 5;               // 0..15
            int c4 = (idx & 31) * 4;         // 0..124
            *(float4*)&Bs[kr][c4] = *(const float4*)(Wr + (size_t)(k0 + kr) * 128 + c4);
        }
        __syncthreads();
#pragma unroll
        for (int kk = 0; kk < 16; kk++) {
            float4 m0 = *(const float4*)&As[kk][tRow * 8];
            float4 m1 = *(const float4*)&As[kk][tRow * 8 + 4];
            float4 n0 = *(const float4*)&Bs[kk][tCol * 8];
            float4 n1 = *(const float4*)&Bs[kk][tCol * 8 + 4];
            float rm[8] = {m0.x, m0.y, m0.z, m0.w, m1.x, m1.y, m1.z, m1.w};
            float rn[8] = {n0.x, n0.y, n0.z, n0.w, n1.x, n1.y, n1.z, n1.w};
#pragma unroll
            for (int i = 0; i < 8; i++)
#pragma unroll
                for (int j = 0; j < 8; j++) acc[i][j] += rm[i] * rn[j];
        }
        __syncthreads();
    }

    // epilogue: scale by nd, add bias, write out, accumulate column stats
    float csum[8], csq[8];
#pragma unroll
    for (int j = 0; j < 8; j++) { csum[j] = 0.f; csq[j] = 0.f; }
#pragma unroll
    for (int i = 0; i < 8; i++) {
        int gr = rowBase + tRow * 8 + i;
        if (gr < m) {
            float ndv = nd[gr];
            float vv[8];
#pragma unroll
            for (int j = 0; j < 8; j++) {
                float v = acc[i][j] * ndv + bias[tCol * 8 + j];
                vv[j] = v;
                csum[j] += v;
                csq[j] += v * v;
            }
            *(float4*)(out + (size_t)gr * 128 + tCol * 8) =
                make_float4(vv[0], vv[1], vv[2], vv[3]);
            *(float4*)(out + (size_t)gr * 128 + tCol * 8 + 4) =
                make_float4(vv[4], vv[5], vv[6], vv[7]);
        }
    }
#pragma unroll
    for (int j = 0; j < 8; j++) {
        atomicAdd(&s_sum[tCol * 8 + j], csum[j]);
        atomicAdd(&s_sq[tCol * 8 + j], csq[j]);
    }
    __syncthreads();
    if (tid < 128) {
        atomicAdd(&stats[tid], s_sum[tid]);
        atomicAdd(&stats[128 + tid], s_sq[tid]);
    }
}

__global__ void k_finalize(const float* __restrict__ stats,
                           const float* __restrict__ gamma, const float* __restrict__ beta,
                           float n, float* __restrict__ scale, float* __restrict__ shift) {
    int c = threadIdx.x;
    float mu = stats[c] / n;
    float var = stats[128 + c] / n - mu * mu;
    float inv = rsqrtf(var + BN_EPS);
    float sc = inv * gamma[c];
    scale[c] = sc;
    shift[c] = beta[c] - mu * sc;
}

__global__ void k_norm_acc(const float* __restrict__ out, float* __restrict__ acc,
                           const float* __restrict__ scale, const float* __restrict__ shift,
                           int n) {
    int i = blockIdx.x * blockDim.x + threadIdx.x;
    int total = n * 32;  // float4 per row = 32
    if (i >= total) return;
    int c4 = i & 31;
    float4 v = ((const float4*)out)[i];
    float4 a = ((float4*)acc)[i];
    float4 sc = ((const float4*)scale)[c4];
    float4 sh = ((const float4*)shift)[c4];
    a.x += v.x * sc.x + sh.x;
    a.y += v.y * sc.y + sh.y;
    a.z += v.z * sc.z + sh.z;
    a.w += v.w * sc.w + sh.w;
    ((float4*)acc)[i] = a;
}

__global__ void k_add(const float4* __restrict__ a, const float4* __restrict__ b,
                      float4* __restrict__ o, int n4) {
    int i = blockIdx.x * blockDim.x + threadIdx.x;
    if (i >= n4) return;
    float4 x = a[i], y = b[i];
    o[i] = make_float4(x.x + y.x, x.y + y.y, x.z + y.z, x.w + y.w);
}

// ---------------- host orchestration ----------------
static inline int cdiv(int a, int b) { return (a + b - 1) / b; }

extern "C" void kernel_launch(void* const* d_in, const int* in_sizes, int n_in,
                              void* d_out, int out_size) {
    const float* fa = (const float*)d_in[0];
    const float* fb = (const float*)d_in[1];
    const float* fg = (const float*)d_in[2];
    const float* W = (const float*)d_in[3];
    const float* bias = (const float*)d_in[4];
    const float* gamma = (const float*)d_in[5];
    const float* beta = (const float*)d_in[6];
    const int* esrc[9];
    const int* edst[9];
    for (int r = 0; r < 9; r++) {
        esrc[r] = (const int*)d_in[7 + 2 * r];
        edst[r] = (const int*)d_in[8 + 2 * r];
    }

    static const int rel_st[9] = {0, 1, 0, 2, 1, 2, 0, 1, 2};
    static const int rel_dt[9] = {1, 0, 2, 0, 2, 1, 0, 1, 2};
    static const int rel_ne[9] = {300000, 300000, 100000, 100000,
                                  150000, 150000, 100000, 150000, 2000};
    static const int ntype[3] = {NA, NB, NG};
    static const int toff[3] = {0, NA, NA + NB};

    int soff[9], doff[9];
    {
        int s = 0, d = 0;
        for (int r = 0; r < 9; r++) {
            soff[r] = s; s += ntype[rel_st[r]];
            doff[r] = d; d += ntype[rel_dt[r]];
        }
    }

    float *p_ns, *p_nd, *p_m, *p_gout, *p_feat, *p_acc, *p_stats, *p_scale, *p_shift;
    cudaGetSymbolAddress((void**)&p_ns, g_ns);
    cudaGetSymbolAddress((void**)&p_nd, g_nd);
    cudaGetSymbolAddress((void**)&p_m, g_m);
    cudaGetSymbolAddress((void**)&p_gout, g_gout);
    cudaGetSymbolAddress((void**)&p_feat, g_feat);
    cudaGetSymbolAddress((void**)&p_acc, g_acc);
    cudaGetSymbolAddress((void**)&p_stats, g_stats);
    cudaGetSymbolAddress((void**)&p_scale, g_scale);
    cudaGetSymbolAddress((void**)&p_shift, g_shift);

    const int TB = 256;

    // ---- degree norms (recomputed each launch; deterministic work) ----
    k_zero4<<<cdiv(DEG_TOT / 4, TB), TB>>>((float4*)p_ns, DEG_TOT / 4);
    k_zero4<<<cdiv(DEG_TOT / 4, TB), TB>>>((float4*)p_nd, DEG_TOT / 4);
    for (int r = 0; r < 9; r++)
        k_count<<<cdiv(rel_ne[r], TB), TB>>>(esrc[r], edst[r], rel_ne[r],
                                             p_ns + soff[r], p_nd + doff[r]);
    k_rsqrt<<<cdiv(DEG_TOT, TB), TB>>>(p_ns, DEG_TOT);
    k_rsqrt<<<cdiv(DEG_TOT, TB), TB>>>(p_nd, DEG_TOT);

    // ---- two layers ----
    const float* layer_feat[3];
    for (int l = 0; l < 2; l++) {
        float* acc = (l == 0) ? p_feat : p_acc;
        if (l == 0) {
            layer_feat[0] = fa; layer_feat[1] = fb; layer_feat[2] = fg;
        } else {
            layer_feat[0] = p_feat;
            layer_feat[1] = p_feat + (size_t)NA * D;
            layer_feat[2] = p_feat + (size_t)(NA + NB) * D;
        }
        k_zero4<<<cdiv(NTOT * D / 4, TB), TB>>>((float4*)acc, NTOT * D / 4);

        for (int r = 0; r < 9; r++) {
            int ne = rel_ne[r];
            int ndst = ntype[rel_dt[r]];
            k_zero4<<<cdiv(ndst * D / 4, TB), TB>>>((float4*)p_m, ndst * D / 4);
            k_zero4<<<1, 64>>>((float4*)p_stats, 64);

            k_scatter<<<cdiv(ne, TB / 32), TB>>>(layer_feat[rel_st[r]], esrc[r], edst[r],
                                                 p_ns + soff[r], p_m, ne);

            const float* Wr = W + ((size_t)l * 9 + r) * D * D;
            const float* br = bias + ((size_t)l * 9 + r) * D;
            const float* gr = gamma + ((size_t)l * 9 + r) * D;
            const float* ber = beta + ((size_t)l * 9 + r) * D;

            k_gemm_bn<<<cdiv(ndst, 128), 256>>>(p_m, Wr, p_nd + doff[r], br,
                                                p_gout, p_stats, ndst);
            k_finalize<<<1, 128>>>(p_stats, gr, ber, (float)ndst, p_scale, p_shift);
            k_norm_acc<<<cdiv(ndst * 32, TB), TB>>>(p_gout,
                                                    acc + (size_t)toff[rel_dt[r]] * D,
                                                    p_scale, p_shift, ndst);
        }
    }

    // ---- residual + final output ----
    float* o = (float*)d_out;
    k_add<<<cdiv(NA * D / 4, TB), TB>>>((const float4*)p_acc, (const float4*)fa,
                                        (float4*)o, NA * D / 4);
    k_add<<<cdiv(NB * D / 4, TB), TB>>>((const float4*)(p_acc + (size_t)NA * D),
                                        (const float4*)fb,
                                        (float4*)(o + (size_t)NA * D), NB * D / 4);
    k_add<<<cdiv(NG * D / 4, TB), TB>>>((const float4*)(p_acc + (size_t)(NA + NB) * D),
                                        (const float4*)fg,
                                        (float4*)(o + (size_t)(NA + NB) * D), NG * D / 4);
}

// round 3
// speedup vs baseline: 1.2554x; 1.2554x over previous
#include <cuda_runtime.h>
#include <cuda_bf16.h>
#include <cstdint>

#define D 128
#define NA 100000
#define NB 150000
#define NG 2000
#define NTOT (NA + NB + NG)      // 252000
#define MAXN NB
#define DEG_TOT 756000           // sum over rels of n_dst (per layer)
#define BN_EPS 1e-5f

// ---------------- device scratch ----------------
__device__ float g_ns[DEG_TOT];
__device__ float g_nd[DEG_TOT];
__device__ float g_m[(size_t)MAXN * D];
__device__ float g_gout[(size_t)DEG_TOT * D];     // per-rel gout, dst-major offsets
__device__ float g_feat[(size_t)NTOT * D];        // layer-0 output
__device__ float g_stats[9 * 2 * D];              // per-rel col sum / sumsq
__device__ float g_scale[9 * D];
__device__ float g_shift[9 * D];
__device__ __nv_bfloat16 g_wh[18 * D * D];        // pre-split W hi (swizzled B-tile layout)
__device__ __nv_bfloat16 g_wl[18 * D * D];        // pre-split W lo

__device__ const int d_ndst[9] = {NB, NA, NG, NA, NG, NB, NA, NB, NG};

// ---------------- layout helpers ----------------
__device__ __forceinline__ uint32_t sw128(uint32_t o) { return o ^ ((o >> 3) & 0x70); }
// 128x128 bf16 tile as two [128 rows x 64 k] half-tiles (16KB each), 128B swizzled rows
__device__ __forceinline__ uint32_t toff128(uint32_t row, uint32_t k) {
    return ((k >> 6) << 14) + sw128(row * 128 + ((k & 63) << 1));
}

__device__ __forceinline__ uint32_t smem_u32(const void* p) {
    uint32_t a;
    asm("{ .reg .u64 t; cvta.to.shared.u64 t, %1; cvt.u32.u64 %0, t; }" : "=r"(a) : "l"(p));
    return a;
}

__device__ __forceinline__ void ldsm4(uint32_t& r0, uint32_t& r1, uint32_t& r2, uint32_t& r3,
                                      uint32_t addr) {
    asm volatile("ldmatrix.sync.aligned.m8n8.x4.shared.b16 {%0,%1,%2,%3}, [%4];"
                 : "=r"(r0), "=r"(r1), "=r"(r2), "=r"(r3) : "r"(addr));
}

__device__ __forceinline__ void mma_bf16(float* d, const uint32_t* a, uint32_t b0, uint32_t b1) {
    asm volatile(
        "mma.sync.aligned.m16n8k16.row.col.f32.bf16.bf16.f32 "
        "{%0,%1,%2,%3}, {%4,%5,%6,%7}, {%8,%9}, {%0,%1,%2,%3};"
        : "+f"(d[0]), "+f"(d[1]), "+f"(d[2]), "+f"(d[3])
        : "r"(a[0]), "r"(a[1]), "r"(a[2]), "r"(a[3]), "r"(b0), "r"(b1));
}

// ---------------- small kernels ----------------
__global__ void k_zero4(float4* p, int n4) {
    int i = blockIdx.x * blockDim.x + threadIdx.x;
    if (i < n4) p[i] = make_float4(0.f, 0.f, 0.f, 0.f);
}

__global__ void k_count(const int* __restrict__ src, const int* __restrict__ dst,
                        int ne, float* __restrict__ cs, float* __restrict__ cd) {
    int e = blockIdx.x * blockDim.x + threadIdx.x;
    if (e < ne) {
        atomicAdd(&cs[src[e]], 1.f);
        atomicAdd(&cd[dst[e]], 1.f);
    }
}

__global__ void k_rsqrt(float* p, int n) {
    int i = blockIdx.x * blockDim.x + threadIdx.x;
    if (i < n) {
        float c = p[i];
        p[i] = (c > 0.f) ? rsqrtf(c) : 0.f;
    }
}

// split W (fp32 [18][k][n]) into bf16 hi/lo stored as B tile [n][k], swizzled
__global__ void k_wsplit(const float* __restrict__ W) {
    int rel = blockIdx.x;  // 0..17
    const float* w = W + (size_t)rel * D * D;
    char* wh = (char*)g_wh + (size_t)rel * D * D * 2;
    char* wl = (char*)g_wl + (size_t)rel * D * D * 2;
    for (int idx = threadIdx.x; idx < D * D; idx += blockDim.x) {
        int k = idx >> 7, n = idx & 127;
        float x = w[idx];
        __nv_bfloat16 h = __float2bfloat16(x);
        __nv_bfloat16 l = __float2bfloat16(x - __bfloat162float(h));
        uint32_t off = toff128(n, k);
        *(__nv_bfloat16*)(wh + off) = h;
        *(__nv_bfloat16*)(wl + off) = l;
    }
}

// one warp per edge, vector RED scatter
__global__ void k_scatter(const float* __restrict__ feat,
                          const int* __restrict__ src, const int* __restrict__ dst,
                          const float* __restrict__ ns, float* __restrict__ m, int ne) {
    int e = blockIdx.x * (blockDim.x >> 5) + (threadIdx.x >> 5);
    int lane = threadIdx.x & 31;
    if (e >= ne) return;
    int s = __ldg(src + e);
    int d = __ldg(dst + e);
    float w = __ldg(ns + s);
    float4 v = __ldg((const float4*)(feat + (size_t)s * D + lane * 4));
    float* p = m + (size_t)d * D + lane * 4;
    asm volatile("red.global.add.v4.f32 [%0], {%1, %2, %3, %4};"
                 :: "l"(p), "f"(v.x * w), "f"(v.y * w), "f"(v.z * w), "f"(v.w * w)
                 : "memory");
}

// ---------------- mma.sync GEMM + fused epilogue ----------------
// out[gr] = (A[gr] @ W) * nd[gr] + bias ; col sum/sumsq -> stats
// A fp32 -> bf16 hi/lo; D = Ahi*Bhi + Ahi*Blo + Alo*Bhi (fp32 accumulators)
#define OFF_AHI  0
#define OFF_ALO  32768
#define OFF_BHI  65536
#define OFF_BLO  98304
#define OFF_BIAS 131072
#define OFF_STAT 131584
#define SMEM_DYN (131584 + 1024 + 1024)

__global__ __launch_bounds__(256, 1)
void k_gemm_mma(const float* __restrict__ A,
                const __nv_bfloat16* __restrict__ whi, const __nv_bfloat16* __restrict__ wlo,
                const float* __restrict__ nd, const float* __restrict__ bias,
                float* __restrict__ out, float* __restrict__ stats, int mrows) {
    extern __shared__ char smem_raw[];
    char* smem = (char*)((((uintptr_t)smem_raw) + 1023) & ~(uintptr_t)1023);
    uint32_t sa = smem_u32(smem);
    int tid = threadIdx.x;
    int lane = tid & 31;
    int wid = tid >> 5;
    int rowBase = blockIdx.x * 128;

    // B (pre-split, pre-swizzled) -> smem
    {
        const uint4* bh = (const uint4*)whi;
        const uint4* bl = (const uint4*)wlo;
        uint4* sh = (uint4*)(smem + OFF_BHI);
        uint4* sl = (uint4*)(smem + OFF_BLO);
#pragma unroll
        for (int i = 0; i < 8; i++) {
            sh[tid + i * 256] = bh[tid + i * 256];
            sl[tid + i * 256] = bl[tid + i * 256];
        }
    }
    // bias + stats smem init
    if (tid < 128) ((float*)(smem + OFF_BIAS))[tid] = bias[tid];
    ((float*)(smem + OFF_STAT))[tid] = 0.f;

    // A: fp32 -> bf16 hi/lo, swizzled. thread t: row t/2, k-half (t&1)*64
    {
        int row = tid >> 1;
        int gr = rowBase + row;
        int kh = (tid & 1) * 64;
        char* ah = smem + OFF_AHI;
        char* al = smem + OFF_ALO;
#pragma unroll
        for (int k = 0; k < 64; k += 4) {
            float4 v = make_float4(0.f, 0.f, 0.f, 0.f);
            if (gr < mrows) v = *(const float4*)(A + (size_t)gr * D + kh + k);
            __nv_bfloat16 hx = __float2bfloat16(v.x), hy = __float2bfloat16(v.y);
            __nv_bfloat16 hz = __float2bfloat16(v.z), hw = __float2bfloat16(v.w);
            __nv_bfloat162 h0; h0.x = hx; h0.y = hy;
            __nv_bfloat162 h1; h1.x = hz; h1.y = hw;
            __nv_bfloat162 l0, l1;
            l0.x = __float2bfloat16(v.x - __bfloat162float(hx));
            l0.y = __float2bfloat16(v.y - __bfloat162float(hy));
            l1.x = __float2bfloat16(v.z - __bfloat162float(hz));
            l1.y = __float2bfloat16(v.w - __bfloat162float(hw));
            uint32_t o0 = toff128(row, kh + k);
            uint32_t o1 = toff128(row, kh + k + 2);
            *(__nv_bfloat162*)(ah + o0) = h0;
            *(__nv_bfloat162*)(ah + o1) = h1;
            *(__nv_bfloat162*)(al + o0) = l0;
            *(__nv_bfloat162*)(al + o1) = l1;
        }
    }
    __syncthreads();

    // warp w: rows [w*16, w*16+16), all 128 cols
    float acc[16][4];
#pragma unroll
    for (int t = 0; t < 16; t++)
#pragma unroll
        for (int j = 0; j < 4; j++) acc[t][j] = 0.f;

    int m0 = wid * 16;
    uint32_t rowA = m0 + (lane & 15);
    uint32_t kA = (lane >> 4) << 3;
    uint32_t rowB = (lane & 7) + ((lane >> 4) << 3);
    uint32_t kB = ((lane >> 3) & 1) << 3;

    const uint32_t abase[3] = {sa + OFF_AHI, sa + OFF_AHI, sa + OFF_ALO};
    const uint32_t bbase[3] = {sa + OFF_BHI, sa + OFF_BLO, sa + OFF_BHI};

#pragma unroll
    for (int s = 0; s < 3; s++) {
        uint32_t ab = abase[s];
        uint32_t bb = bbase[s];
#pragma unroll
        for (int k0 = 0; k0 < 128; k0 += 16) {
            uint32_t a[4];
            ldsm4(a[0], a[1], a[2], a[3], ab + toff128(rowA, k0 + kA));
#pragma unroll
            for (int nn = 0; nn < 8; nn++) {
                uint32_t b0, b1, b2, b3;
                ldsm4(b0, b1, b2, b3, bb + toff128(nn * 16 + rowB, k0 + kB));
                mma_bf16(acc[2 * nn], a, b0, b1);
                mma_bf16(acc[2 * nn + 1], a, b2, b3);
            }
        }
    }

    // epilogue: thread holds rows (m0+quad, m0+quad+8), cols 8t+cp, 8t+cp+1
    int quad = lane >> 2;
    int cp = (lane & 3) * 2;
    int gr0 = rowBase + m0 + quad;
    int gr1 = gr0 + 8;
    bool v0 = gr0 < mrows, v1 = gr1 < mrows;
    float nd0 = v0 ? nd[gr0] : 0.f;
    float nd1 = v1 ? nd[gr1] : 0.f;
    const float* sbias = (const float*)(smem + OFF_BIAS);
    float* sstat = (float*)(smem + OFF_STAT);

#pragma unroll
    for (int t = 0; t < 16; t++) {
        int c = t * 8 + cp;
        float b0 = sbias[c], b1 = sbias[c + 1];
        float x0 = acc[t][0] * nd0 + b0, x1 = acc[t][1] * nd0 + b1;
        float y0 = acc[t][2] * nd1 + b0, y1 = acc[t][3] * nd1 + b1;
        if (v0) *(float2*)(out + (size_t)gr0 * D + c) = make_float2(x0, x1);
        if (v1) *(float2*)(out + (size_t)gr1 * D + c) = make_float2(y0, y1);
        float s0 = (v0 ? x0 : 0.f) + (v1 ? y0 : 0.f);
        float s1 = (v0 ? x1 : 0.f) + (v1 ? y1 : 0.f);
        float q0 = (v0 ? x0 * x0 : 0.f) + (v1 ? y0 * y0 : 0.f);
        float q1 = (v0 ? x1 * x1 : 0.f) + (v1 ? y1 * y1 : 0.f);
#pragma unroll
        for (int S = 4; S <= 16; S <<= 1) {
            s0 += __shfl_xor_sync(0xffffffffu, s0, S);
            s1 += __shfl_xor_sync(0xffffffffu, s1, S);
            q0 += __shfl_xor_sync(0xffffffffu, q0, S);
            q1 += __shfl_xor_sync(0xffffffffu, q1, S);
        }
        if (lane < 4) {
            atomicAdd(&sstat[c], s0);
            atomicAdd(&sstat[c + 1], s1);
            atomicAdd(&sstat[128 + c], q0);
            atomicAdd(&sstat[128 + c + 1], q1);
        }
    }
    __syncthreads();
    atomicAdd(&stats[tid], sstat[tid]);
}

// per-rel BN scale/shift from stats
__global__ void k_finalize9(const float* __restrict__ gammaL, const float* __restrict__ betaL) {
    int r = blockIdx.x;
    int c = threadIdx.x;
    float n = (float)d_ndst[r];
    float mu = g_stats[r * 256 + c] / n;
    float var = g_stats[r * 256 + 128 + c] / n - mu * mu;
    float inv = rsqrtf(var + BN_EPS);
    float sc = inv * gammaL[r * D + c];
    g_scale[r * D + c] = sc;
    g_shift[r * D + c] = betaL[r * D + c] - mu * sc;
}

// fused: out = sum_{3 rels} gout_s * scale_s + shift_s (+ resid)
__global__ void k_fuse3(const float4* __restrict__ g0, const float4* __restrict__ g1,
                        const float4* __restrict__ g2,
                        const float* __restrict__ sc0, const float* __restrict__ sc1,
                        const float* __restrict__ sc2,
                        const float* __restrict__ sh0, const float* __restrict__ sh1,
                        const float* __restrict__ sh2,
                        const float4* __restrict__ resid, float4* __restrict__ out, int n) {
    int i = blockIdx.x * blockDim.x + threadIdx.x;
    int total = n * 32;
    if (i >= total) return;
    int c = (i & 31) * 4;
    float4 a = g0[i], b = g1[i], g = g2[i];
    float4 o;
    o.x = a.x * sc0[c + 0] + b.x * sc1[c + 0] + g.x * sc2[c + 0] + sh0[c + 0] + sh1[c + 0] + sh2[c + 0];
    o.y = a.y * sc0[c + 1] + b.y * sc1[c + 1] + g.y * sc2[c + 1] + sh0[c + 1] + sh1[c + 1] + sh2[c + 1];
    o.z = a.z * sc0[c + 2] + b.z * sc1[c + 2] + g.z * sc2[c + 2] + sh0[c + 2] + sh1[c + 2] + sh2[c + 2];
    o.w = a.w * sc0[c + 3] + b.w * sc1[c + 3] + g.w * sc2[c + 3] + sh0[c + 3] + sh1[c + 3] + sh2[c + 3];
    if (resid) {
        float4 rr = resid[i];
        o.x += rr.x; o.y += rr.y; o.z += rr.z; o.w += rr.w;
    }
    out[i] = o;
}

// ---------------- host orchestration ----------------
static inline int cdiv(int a, int b) { return (a + b - 1) / b; }

extern "C" void kernel_launch(void* const* d_in, const int* in_sizes, int n_in,
                              void* d_out, int out_size) {
    const float* fa = (const float*)d_in[0];
    const float* fb = (const float*)d_in[1];
    const float* fg = (const float*)d_in[2];
    const float* W = (const float*)d_in[3];
    const float* bias = (const float*)d_in[4];
    const float* gamma = (const float*)d_in[5];
    const float* beta = (const float*)d_in[6];
    const int* esrc[9];
    const int* edst[9];
    for (int r = 0; r < 9; r++) {
        esrc[r] = (const int*)d_in[7 + 2 * r];
        edst[r] = (const int*)d_in[8 + 2 * r];
    }

    static const int rel_st[9] = {0, 1, 0, 2, 1, 2, 0, 1, 2};
    static const int rel_dt[9] = {1, 0, 2, 0, 2, 1, 0, 1, 2};
    static const int rel_ne[9] = {300000, 300000, 100000, 100000,
                                  150000, 150000, 100000, 150000, 2000};
    static const int ntype[3] = {NA, NB, NG};
    static const int toff[3] = {0, NA, NA + NB};
    static const int dt_rels[3][3] = {{1, 3, 6}, {0, 5, 7}, {2, 4, 8}};

    int soff[9], doff[9];
    {
        int s = 0, d = 0;
        for (int r = 0; r < 9; r++) {
            soff[r] = s; s += ntype[rel_st[r]];
            doff[r] = d; d += ntype[rel_dt[r]];
        }
    }

    float *p_ns, *p_nd, *p_m, *p_gout, *p_feat, *p_stats, *p_scale, *p_shift;
    __nv_bfloat16 *p_wh, *p_wl;
    cudaGetSymbolAddress((void**)&p_ns, g_ns);
    cudaGetSymbolAddress((void**)&p_nd, g_nd);
    cudaGetSymbolAddress((void**)&p_m, g_m);
    cudaGetSymbolAddress((void**)&p_gout, g_gout);
    cudaGetSymbolAddress((void**)&p_feat, g_feat);
    cudaGetSymbolAddress((void**)&p_stats, g_stats);
    cudaGetSymbolAddress((void**)&p_scale, g_scale);
    cudaGetSymbolAddress((void**)&p_shift, g_shift);
    cudaGetSymbolAddress((void**)&p_wh, g_wh);
    cudaGetSymbolAddress((void**)&p_wl, g_wl);

    cudaFuncSetAttribute(k_gemm_mma, cudaFuncAttributeMaxDynamicSharedMemorySize, SMEM_DYN);

    const int TB = 256;

    // degree norms
    k_zero4<<<cdiv(DEG_TOT / 4, TB), TB>>>((float4*)p_ns, DEG_TOT / 4);
    k_zero4<<<cdiv(DEG_TOT / 4, TB), TB>>>((float4*)p_nd, DEG_TOT / 4);
    for (int r = 0; r < 9; r++)
        k_count<<<cdiv(rel_ne[r], TB), TB>>>(esrc[r], edst[r], rel_ne[r],
                                             p_ns + soff[r], p_nd + doff[r]);
    k_rsqrt<<<cdiv(DEG_TOT, TB), TB>>>(p_ns, DEG_TOT);
    k_rsqrt<<<cdiv(DEG_TOT, TB), TB>>>(p_nd, DEG_TOT);

    // pre-split weights (hi/lo bf16, swizzled B-tile layout)
    k_wsplit<<<18, 256>>>(W);

    const float* layer_feat[3];
    for (int l = 0; l < 2; l++) {
        if (l == 0) {
            layer_feat[0] = fa; layer_feat[1] = fb; layer_feat[2] = fg;
        } else {
            layer_feat[0] = p_feat;
            layer_feat[1] = p_feat + (size_t)NA * D;
            layer_feat[2] = p_feat + (size_t)(NA + NB) * D;
        }

        k_zero4<<<cdiv(9 * 256 / 4, TB), TB>>>((float4*)p_stats, 9 * 256 / 4);

        for (int r = 0; r < 9; r++) {
            int ne = rel_ne[r];
            int ndst = ntype[rel_dt[r]];
            k_zero4<<<cdiv(ndst * D / 4, TB), TB>>>((float4*)p_m, ndst * D / 4);
            k_scatter<<<cdiv(ne, TB / 32), TB>>>(layer_feat[rel_st[r]], esrc[r], edst[r],
                                                 p_ns + soff[r], p_m, ne);
            int lr = l * 9 + r;
            k_gemm_mma<<<cdiv(ndst, 128), 256, SMEM_DYN>>>(
                p_m, p_wh + (size_t)lr * D * D, p_wl + (size_t)lr * D * D,
                p_nd + doff[r], bias + (size_t)lr * D,
                p_gout + (size_t)doff[r] * D, p_stats + r * 256, ndst);
        }

        k_finalize9<<<9, 128>>>(gamma + (size_t)l * 9 * D, beta + (size_t)l * 9 * D);

        const float* resid_t[3] = {fa, fb, fg};
        for (int t = 0; t < 3; t++) {
            int n = ntype[t];
            const int* rl = dt_rels[t];
            float* outp = (l == 0) ? (p_feat + (size_t)toff[t] * D)
                                   : ((float*)d_out + (size_t)toff[t] * D);
            k_fuse3<<<cdiv(n * 32, TB), TB>>>(
                (const float4*)(p_gout + (size_t)doff[rl[0]] * D),
                (const float4*)(p_gout + (size_t)doff[rl[1]] * D),
                (const float4*)(p_gout + (size_t)doff[rl[2]] * D),
                p_scale + rl[0] * D, p_scale + rl[1] * D, p_scale + rl[2] * D,
                p_shift + rl[0] * D, p_shift + rl[1] * D, p_shift + rl[2] * D,
                (l == 0) ? nullptr : (const float4*)resid_t[t],
                (float4*)outp, n);
        }
    }
}